// round 15
// baseline (speedup 1.0000x reference)
#include <cuda_runtime.h>
#include <cuda_fp16.h>

#define RR 256
#define TT 32
#define BB 32
#define YSZ 64

#define TILE 64
#define XS 68      // x tile with halo 2 on each side
#define HS 66      // conv1 output tile (halo 1 for conv2)
#define HSTR 68    // padded stride (half2 elements) for 16B-aligned reads
#define CH 4       // channels per hs pass (2 half2 pair-tiles)

#define XS_FLOATS   (XS * XS)          // 4624
#define HS_ELEMS    (HS * HSTR)        // 4488 half2 entries per pair-tile
#define SMEM_FLOATS (XS_FLOATS + 2 * HS_ELEMS + 288 + 288 + 32 + 1)
#define SMEM_BYTES  (SMEM_FLOATS * 4)  // 56836 -> 3 CTAs/SM

// 8MB scratch for stage-1 output (device global: no allocation)
__device__ float g_x[BB * RR * RR];

// ---------------------------------------------------------------------------
// Stage 1: x[b,p,q] = sum_t Ht[t,p,q] * yt[b,t,p>>2,q>>2]
// (R9 proven version: 4 batches/CTA, static smem)
// ---------------------------------------------------------------------------
__global__ __launch_bounds__(256) void stage1_kernel(
    const float* __restrict__ yt, const float* __restrict__ Ht)
{
    __shared__ float s_yt[4][TT][YSZ];   // 32 KB

    const int p   = blockIdx.x;
    const int bg  = blockIdx.y;
    const int tid = threadIdx.x;
    const int yr  = p >> 2;

    for (int i = tid; i < 4 * TT * YSZ; i += 256) {
        int q4 = i & 63;
        int t  = (i >> 6) & 31;
        int bl = i >> 11;
        s_yt[bl][t][q4] = yt[(((bg * 4 + bl) * TT + t) * YSZ + yr) * YSZ + q4];
    }
    __syncthreads();

    const int q  = tid;
    const int q4 = q >> 2;
    const float* hp = Ht + p * RR + q;

    float a0 = 0.f, a1 = 0.f, a2 = 0.f, a3 = 0.f;
#pragma unroll
    for (int t = 0; t < TT; t++) {
        float h = hp[t * RR * RR];
        a0 = fmaf(h, s_yt[0][t][q4], a0);
        a1 = fmaf(h, s_yt[1][t][q4], a1);
        a2 = fmaf(h, s_yt[2][t][q4], a2);
        a3 = fmaf(h, s_yt[3][t][q4], a3);
    }
    float* xp = g_x + (bg * 4) * RR * RR + p * RR + q;
    xp[0 * RR * RR] = a0;
    xp[1 * RR * RR] = a1;
    xp[2 * RR * RR] = a2;
    xp[3 * RR * RR] = a3;
}

// ---------------------------------------------------------------------------
// Conv(1->32,3x3) -> ReLU -> Conv(32->1,3x3), fused, CH=4 per pass.
// conv1: fp32 math, 6-row sliding walks (3 LDS/pt), hs stored as half2
//        channel pairs (STS halved). conv2: half2 reads -> fp32 acc.
// Grid: (4, 4, 32). 256 threads. 56.8 KB dyn smem -> 3 CTAs/SM.
// ---------------------------------------------------------------------------
__global__ __launch_bounds__(256, 3) void conv_fused_kernel(
    const float* __restrict__ W1, const float* __restrict__ b1,
    const float* __restrict__ W2, const float* __restrict__ b2,
    float* __restrict__ out)
{
    extern __shared__ float smem[];
    float* xs      = smem;                               // 68x68 fp32
    __half2* hsb   = (__half2*)(smem + XS_FLOATS);       // 2 pair-tiles 66x68
    float* w1s     = smem + XS_FLOATS + 2 * HS_ELEMS;    // 288
    float* w2s     = w1s + 288;                          // 288
    float* b1s     = w2s + 288;                          // 32
    float* b2s     = b1s + 32;                           // 1

    const int b   = blockIdx.z;
    const int ty0 = blockIdx.y * TILE;
    const int tx0 = blockIdx.x * TILE;
    const int tid = threadIdx.x;

    for (int i = tid; i < 288; i += 256) { w1s[i] = W1[i]; w2s[i] = W2[i]; }
    if (tid < 32)  b1s[tid] = b1[tid];
    if (tid == 0)  b2s[0] = b2[0];

    // Load x tile with halo 2 (zero-pad at image borders)
    const float* xb = g_x + b * RR * RR;
    for (int i = tid; i < XS_FLOATS; i += 256) {
        int ry = i / XS, rx = i - ry * XS;
        int gy = ty0 - 2 + ry, gx = tx0 - 2 + rx;
        float v = 0.f;
        if (gy >= 0 && gy < RR && gx >= 0 && gx < RR) v = xb[gy * RR + gx];
        xs[i] = v;
    }
    __syncthreads();

    const int tx = tid & 15;
    const int ty = tid >> 4;
    const int ox = tx * 4;
    const int oy = ty * 4;

    float acc[4][4];
#pragma unroll
    for (int i = 0; i < 4; i++)
#pragma unroll
        for (int j = 0; j < 4; j++) acc[i][j] = 0.f;

    for (int g = 0; g < 32 / CH; g++) {
        const int c0 = g * CH;

        float w1r[CH][9], bcr[CH];
#pragma unroll
        for (int cc = 0; cc < CH; cc++) {
#pragma unroll
            for (int k = 0; k < 9; k++) w1r[cc][k] = w1s[(c0 + cc) * 9 + k];
            bcr[cc] = b1s[c0 + cc];
        }

        // --- conv1: 11 bands x 66 cols of 6-row vertical sliding walks ---
        for (int s = tid; s < 11 * 66; s += 256) {
            int band = s / 66;
            int col  = s - band * 66;
            int r0   = band * 6;
            bool col_oob = ((unsigned)(tx0 + col - 1) >= RR);
            const float* xp = xs + r0 * XS + col;
            __half2* hp = hsb + r0 * HSTR + col;

            float x0 = xp[0],  x1 = xp[1],      x2 = xp[2];
            float x3 = xp[XS], x4 = xp[XS + 1], x5 = xp[XS + 2];
            xp += 2 * XS;

            int gy = ty0 + r0 - 1;
#pragma unroll
            for (int r = 0; r < 6; r++) {
                float x6 = xp[0], x7 = xp[1], x8 = xp[2];
                bool oob = col_oob || ((unsigned)gy >= RR);
                float vv[CH];
#pragma unroll
                for (int cc = 0; cc < CH; cc++) {
                    float v = bcr[cc];
                    v = fmaf(w1r[cc][0], x0, v);
                    v = fmaf(w1r[cc][1], x1, v);
                    v = fmaf(w1r[cc][2], x2, v);
                    v = fmaf(w1r[cc][3], x3, v);
                    v = fmaf(w1r[cc][4], x4, v);
                    v = fmaf(w1r[cc][5], x5, v);
                    v = fmaf(w1r[cc][6], x6, v);
                    v = fmaf(w1r[cc][7], x7, v);
                    v = fmaf(w1r[cc][8], x8, v);
                    float rr = fmaxf(v, 0.f);
                    vv[cc] = oob ? 0.f : rr;
                }
                hp[0]            = __floats2half2_rn(vv[0], vv[1]);
                hp[HS_ELEMS]     = __floats2half2_rn(vv[2], vv[3]);

                hp += HSTR; xp += XS; gy++;
                x0 = x3; x1 = x4; x2 = x5;
                x3 = x6; x4 = x7; x5 = x8;
            }
        }
        __syncthreads();

        // --- conv2: 2 channel pairs, half2 reads, fp32 accumulation ---
#pragma unroll
        for (int pp = 0; pp < 2; pp++) {
            float wa[9], wb[9];
#pragma unroll
            for (int k = 0; k < 9; k++) {
                wa[k] = w2s[(c0 + 2 * pp + 0) * 9 + k];
                wb[k] = w2s[(c0 + 2 * pp + 1) * 9 + k];
            }
            const __half2* hc = hsb + pp * HS_ELEMS;
#pragma unroll
            for (int pr = 0; pr < 6; pr++) {
                const __half2* hq = hc + (oy + pr) * HSTR + ox;
                // 6 half2 = 24B: uint4 (4 half2) + uint2 (2 half2), 16B/8B aligned
                uint4 u4 = *(const uint4*)hq;
                uint2 u2 = *(const uint2*)(hq + 4);
                float2 f0 = __half22float2(*(const __half2*)&u4.x);
                float2 f1 = __half22float2(*(const __half2*)&u4.y);
                float2 f2 = __half22float2(*(const __half2*)&u4.z);
                float2 f3 = __half22float2(*(const __half2*)&u4.w);
                float2 f4 = __half22float2(*(const __half2*)&u2.x);
                float2 f5 = __half22float2(*(const __half2*)&u2.y);
                float ra[6] = { f0.x, f1.x, f2.x, f3.x, f4.x, f5.x };
                float rb[6] = { f0.y, f1.y, f2.y, f3.y, f4.y, f5.y };
#pragma unroll
                for (int i = 0; i < 4; i++) {
                    int dy = pr - i;
                    if (dy >= 0 && dy < 3) {
#pragma unroll
                        for (int j = 0; j < 4; j++) {
                            acc[i][j] = fmaf(wa[dy * 3 + 0], ra[j],     acc[i][j]);
                            acc[i][j] = fmaf(wa[dy * 3 + 1], ra[j + 1], acc[i][j]);
                            acc[i][j] = fmaf(wa[dy * 3 + 2], ra[j + 2], acc[i][j]);
                            acc[i][j] = fmaf(wb[dy * 3 + 0], rb[j],     acc[i][j]);
                            acc[i][j] = fmaf(wb[dy * 3 + 1], rb[j + 1], acc[i][j]);
                            acc[i][j] = fmaf(wb[dy * 3 + 2], rb[j + 2], acc[i][j]);
                        }
                    }
                }
            }
        }
        __syncthreads();   // protect hs before next group overwrites it
    }

    float bb = b2s[0];
#pragma unroll
    for (int i = 0; i < 4; i++) {
        float4 o;
        o.x = acc[i][0] + bb;
        o.y = acc[i][1] + bb;
        o.z = acc[i][2] + bb;
        o.w = acc[i][3] + bb;
        *(float4*)(out + (size_t)(b * RR + ty0 + oy + i) * RR + tx0 + ox) = o;
    }
}

extern "C" void kernel_launch(void* const* d_in, const int* in_sizes, int n_in,
                              void* d_out, int out_size) {
    const float* yt = (const float*)d_in[0];
    const float* Ht = (const float*)d_in[1];
    const float* W1 = (const float*)d_in[2];
    const float* b1 = (const float*)d_in[3];
    const float* W2 = (const float*)d_in[4];
    const float* b2 = (const float*)d_in[5];
    float* out = (float*)d_out;

    // Immediate (non-stream) API: executes at call time, not captured.
    cudaFuncSetAttribute(conv_fused_kernel,
                         cudaFuncAttributeMaxDynamicSharedMemorySize, SMEM_BYTES);

    stage1_kernel<<<dim3(256, 8), 256>>>(yt, Ht);
    conv_fused_kernel<<<dim3(4, 4, 32), 256, SMEM_BYTES>>>(W1, b1, W2, b2, out);
}

// round 16
// speedup vs baseline: 1.2532x; 1.2532x over previous
#include <cuda_runtime.h>

#define RR 256
#define TT 32
#define BB 32
#define YSZ 64

#define TILE 64
#define XS 68      // x tile with halo 2 on each side
#define HS 66      // conv1 output tile (halo 1 for conv2)
#define HSTR 68    // padded stride for 16B-aligned float4 loads
#define CH 4       // channels per hs pass

#define XS_FLOATS   (XS * XS)          // 4624
#define HS_FLOATS   (HS * HSTR)        // 4488
#define SMEM_FLOATS (XS_FLOATS + CH * HS_FLOATS + 288 + 288 + 32 + 1)
#define SMEM_BYTES  (SMEM_FLOATS * 4)  // 92740

// 8MB scratch for stage-1 output (device global: no allocation)
__device__ float g_x[BB * RR * RR];

// ---------------------------------------------------------------------------
// Stage 1: x[b,p,q] = sum_t Ht[t,p,q] * yt[b,t,p>>2,q>>2]
// R16: 4 p-rows per CTA (all share yr=p>>2) -> one yt smem fill serves 4x work.
// Grid: (64, 8). 256 threads = q.
// ---------------------------------------------------------------------------
__global__ __launch_bounds__(256) void stage1_kernel(
    const float* __restrict__ yt, const float* __restrict__ Ht)
{
    __shared__ float s_yt[4][TT][YSZ];   // 32 KB

    const int yr  = blockIdx.x;          // 0..63; serves p = 4*yr .. 4*yr+3
    const int bg  = blockIdx.y;          // group of 4 batches
    const int tid = threadIdx.x;

    for (int i = tid; i < 4 * TT * YSZ; i += 256) {
        int q4 = i & 63;
        int t  = (i >> 6) & 31;
        int bl = i >> 11;
        s_yt[bl][t][q4] = yt[(((bg * 4 + bl) * TT + t) * YSZ + yr) * YSZ + q4];
    }
    __syncthreads();

    const int q  = tid;
    const int q4 = q >> 2;
    const float* hbase = Ht + (yr * 4) * RR + q;   // Ht[t, 4*yr + pp, q]

    float a[4][4];   // [pp][bl]
#pragma unroll
    for (int pp = 0; pp < 4; pp++)
#pragma unroll
        for (int bl = 0; bl < 4; bl++) a[pp][bl] = 0.f;

#pragma unroll 8
    for (int t = 0; t < TT; t++) {
        float y0 = s_yt[0][t][q4];
        float y1 = s_yt[1][t][q4];
        float y2 = s_yt[2][t][q4];
        float y3 = s_yt[3][t][q4];
#pragma unroll
        for (int pp = 0; pp < 4; pp++) {
            float h = hbase[t * RR * RR + pp * RR];
            a[pp][0] = fmaf(h, y0, a[pp][0]);
            a[pp][1] = fmaf(h, y1, a[pp][1]);
            a[pp][2] = fmaf(h, y2, a[pp][2]);
            a[pp][3] = fmaf(h, y3, a[pp][3]);
        }
    }
#pragma unroll
    for (int pp = 0; pp < 4; pp++)
#pragma unroll
        for (int bl = 0; bl < 4; bl++)
            g_x[(bg * 4 + bl) * RR * RR + (yr * 4 + pp) * RR + q] = a[pp][bl];
}

// ---------------------------------------------------------------------------
// Conv(1->32,3x3) -> ReLU -> Conv(32->1,3x3), fused, CH=4 per pass.
// conv1 (R16): 3-row x 2-col walks; taps as aligned float2 (2 LDS.64/row for
//   BOTH columns), outputs as float2 STS.64 per channel. Layout unchanged.
// conv2: scalar 4x4 register tile (R9 proven form, conflict-free).
// Grid: (4, 4, 32). 256 threads. Dynamic smem 92.7 KB, 2 CTAs/SM.
// ---------------------------------------------------------------------------
__global__ __launch_bounds__(256, 2) void conv_fused_kernel(
    const float* __restrict__ W1, const float* __restrict__ b1,
    const float* __restrict__ W2, const float* __restrict__ b2,
    float* __restrict__ out)
{
    extern __shared__ float smem[];
    float* xs  = smem;                        // 68x68
    float* hsb = smem + XS_FLOATS;            // CH * 66x68
    float* w1s = hsb + CH * HS_FLOATS;        // 288
    float* w2s = w1s + 288;                   // 288
    float* b1s = w2s + 288;                   // 32
    float* b2s = b1s + 32;                    // 1

    const int b   = blockIdx.z;
    const int ty0 = blockIdx.y * TILE;
    const int tx0 = blockIdx.x * TILE;
    const int tid = threadIdx.x;

    for (int i = tid; i < 288; i += 256) { w1s[i] = W1[i]; w2s[i] = W2[i]; }
    if (tid < 32)  b1s[tid] = b1[tid];
    if (tid == 0)  b2s[0] = b2[0];

    // Load x tile with halo 2 (zero-pad at image borders)
    const float* xb = g_x + b * RR * RR;
    for (int i = tid; i < XS_FLOATS; i += 256) {
        int ry = i / XS, rx = i - ry * XS;
        int gy = ty0 - 2 + ry, gx = tx0 - 2 + rx;
        float v = 0.f;
        if (gy >= 0 && gy < RR && gx >= 0 && gx < RR) v = xb[gy * RR + gx];
        xs[i] = v;
    }
    __syncthreads();

    const int tx = tid & 15;
    const int ty = tid >> 4;
    const int ox = tx * 4;
    const int oy = ty * 4;

    float acc[4][4];
#pragma unroll
    for (int i = 0; i < 4; i++)
#pragma unroll
        for (int j = 0; j < 4; j++) acc[i][j] = 0.f;

    for (int g = 0; g < 32 / CH; g++) {
        const int c0 = g * CH;

        float w1r[CH][9], bcr[CH];
#pragma unroll
        for (int cc = 0; cc < CH; cc++) {
#pragma unroll
            for (int k = 0; k < 9; k++) w1r[cc][k] = w1s[(c0 + cc) * 9 + k];
            bcr[cc] = b1s[c0 + cc];
        }

        // --- conv1: 22 bands x 33 col-pairs of 3-row x 2-col walks ---
        for (int s = tid; s < 22 * 33; s += 256) {
            int band = s / 33;
            int cp   = s - band * 33;
            int col  = cp * 2;            // even: float2-aligned
            int r0   = band * 3;
            bool c0_oob = ((unsigned)(tx0 + col - 1) >= RR);
            bool c1_oob = ((unsigned)(tx0 + col)     >= RR);

            float2 A0 = *(const float2*)(xs + r0 * XS + col);
            float2 B0 = *(const float2*)(xs + r0 * XS + col + 2);
            float2 A1 = *(const float2*)(xs + (r0 + 1) * XS + col);
            float2 B1 = *(const float2*)(xs + (r0 + 1) * XS + col + 2);
            const float* xrow = xs + (r0 + 2) * XS + col;
            float* hp = hsb + r0 * HSTR + col;
            int gy = ty0 + r0 - 1;

#pragma unroll
            for (int r = 0; r < 3; r++) {
                float2 A2 = *(const float2*)(xrow);
                float2 B2 = *(const float2*)(xrow + 2);
                bool row_oob = ((unsigned)gy >= RR);
#pragma unroll
                for (int cc = 0; cc < CH; cc++) {
                    const float* w = w1r[cc];
                    float v0 = bcr[cc], v1 = bcr[cc];
                    v0 = fmaf(w[0], A0.x, v0);  v1 = fmaf(w[0], A0.y, v1);
                    v0 = fmaf(w[1], A0.y, v0);  v1 = fmaf(w[1], B0.x, v1);
                    v0 = fmaf(w[2], B0.x, v0);  v1 = fmaf(w[2], B0.y, v1);
                    v0 = fmaf(w[3], A1.x, v0);  v1 = fmaf(w[3], A1.y, v1);
                    v0 = fmaf(w[4], A1.y, v0);  v1 = fmaf(w[4], B1.x, v1);
                    v0 = fmaf(w[5], B1.x, v0);  v1 = fmaf(w[5], B1.y, v1);
                    v0 = fmaf(w[6], A2.x, v0);  v1 = fmaf(w[6], A2.y, v1);
                    v0 = fmaf(w[7], A2.y, v0);  v1 = fmaf(w[7], B2.x, v1);
                    v0 = fmaf(w[8], B2.x, v0);  v1 = fmaf(w[8], B2.y, v1);
                    v0 = (row_oob || c0_oob) ? 0.f : fmaxf(v0, 0.f);
                    v1 = (row_oob || c1_oob) ? 0.f : fmaxf(v1, 0.f);
                    *(float2*)(hp + cc * HS_FLOATS) = make_float2(v0, v1);
                }
                hp += HSTR; xrow += XS; gy++;
                A0 = A1; B0 = B1;
                A1 = A2; B1 = B2;
            }
        }
        __syncthreads();

        // --- conv2: accumulate CH channels into 4x4 register tile ---
#pragma unroll
        for (int cc = 0; cc < CH; cc++) {
            float w2r[9];
#pragma unroll
            for (int k = 0; k < 9; k++) w2r[k] = w2s[(c0 + cc) * 9 + k];
            const float* hc = hsb + cc * HS_FLOATS;
#pragma unroll
            for (int pr = 0; pr < 6; pr++) {
                const float* hq = hc + (oy + pr) * HSTR + ox;
                float4 v4 = *(const float4*)hq;
                float2 v2 = *(const float2*)(hq + 4);
                float rv[6] = { v4.x, v4.y, v4.z, v4.w, v2.x, v2.y };
#pragma unroll
                for (int i = 0; i < 4; i++) {
                    int dy = pr - i;
                    if (dy >= 0 && dy < 3) {
#pragma unroll
                        for (int j = 0; j < 4; j++) {
                            acc[i][j] = fmaf(w2r[dy * 3 + 0], rv[j],     acc[i][j]);
                            acc[i][j] = fmaf(w2r[dy * 3 + 1], rv[j + 1], acc[i][j]);
                            acc[i][j] = fmaf(w2r[dy * 3 + 2], rv[j + 2], acc[i][j]);
                        }
                    }
                }
            }
        }
        __syncthreads();   // protect hs before next group overwrites it
    }

    float bb = b2s[0];
#pragma unroll
    for (int i = 0; i < 4; i++) {
        float4 o;
        o.x = acc[i][0] + bb;
        o.y = acc[i][1] + bb;
        o.z = acc[i][2] + bb;
        o.w = acc[i][3] + bb;
        *(float4*)(out + (size_t)(b * RR + ty0 + oy + i) * RR + tx0 + ox) = o;
    }
}

extern "C" void kernel_launch(void* const* d_in, const int* in_sizes, int n_in,
                              void* d_out, int out_size) {
    const float* yt = (const float*)d_in[0];
    const float* Ht = (const float*)d_in[1];
    const float* W1 = (const float*)d_in[2];
    const float* b1 = (const float*)d_in[3];
    const float* W2 = (const float*)d_in[4];
    const float* b2 = (const float*)d_in[5];
    float* out = (float*)d_out;

    // Immediate (non-stream) API: executes at call time, not captured.
    cudaFuncSetAttribute(conv_fused_kernel,
                         cudaFuncAttributeMaxDynamicSharedMemorySize, SMEM_BYTES);

    stage1_kernel<<<dim3(64, 8), 256>>>(yt, Ht);
    conv_fused_kernel<<<dim3(4, 4, 32), 256, SMEM_BYTES>>>(W1, b1, W2, b2, out);
}